// round 4
// baseline (speedup 1.0000x reference)
#include <cuda_runtime.h>
#include <math.h>
#include <string.h>

// ---------------------------------------------------------------------------
// Problem constants
// ---------------------------------------------------------------------------
#define BATCH 4
#define IMG_H 512
#define IMG_W 512
#define PATCH 64
#define STRIDE_ 32
#define NPATCH 256            // (512/32)^2
#define PATCHES_ELEMS (BATCH * NPATCH * 3 * PATCH * PATCH)   // 12,582,912
#define FLOW_ELEMS    (BATCH * 2 * IMG_H * IMG_W)            //  2,097,152
#define DEF_ELEMS     (BATCH * IMG_H * IMG_W * 2)            //  2,097,152

typedef unsigned long long u64;

// Scratch ping-pong buffers (device globals: allocation-free scratch).
__device__ float g_bufA[33554432];
__device__ float g_bufB[33554432];

// ---------------------------------------------------------------------------
// f32x2 packed helpers (ptxas never emits FFMA2 from C++; PTX only)
// ---------------------------------------------------------------------------
__device__ __forceinline__ void fma2(u64& d, u64 a, u64 b) {
    asm("fma.rn.f32x2 %0, %1, %2, %3;" : "=l"(d) : "l"(a), "l"(b), "l"(d));
}
__device__ __forceinline__ u64 pack2(float lo, float hi) {
    u64 r; asm("mov.b64 %0, {%1, %2};" : "=l"(r) : "f"(lo), "f"(hi)); return r;
}
__device__ __forceinline__ float2 unpack2(u64 v) {
    float2 r; asm("mov.b64 {%0, %1}, %2;" : "=f"(r.x), "=f"(r.y) : "l"(v)); return r;
}
__device__ __forceinline__ u64 as_u64(float2 v) {
    u64 r; memcpy(&r, &v, 8); return r;
}

// ---------------------------------------------------------------------------
// Direct 3x3 conv, pad=1, optional ReLU / tanh.  f32x2 packed inner loop.
// Block = 16x16 threads; each thread computes a 2x2 pixel patch for
// COUT_BLK output channels. Accumulators are f32x2 pairs over (x, x+1).
// Weights stored duplicated (w,w) in smem -> one LDS.64 feeds 2 FMA2.
// ACT: 0=none, 1=relu, 2=tanh
// ---------------------------------------------------------------------------
template <int CIN, int COUT, int CIN_BLK, int COUT_BLK, int ACT>
__global__ void __launch_bounds__(256, 3)
conv3x3_kernel(const float* __restrict__ in, const float* __restrict__ wgt,
               const float* __restrict__ bias, float* __restrict__ out,
               int H, int W)
{
    constexpr int TILE = 32;
    constexpr int PITCH = TILE + 4;   // 36 floats: even pitch -> 8B-aligned pairs
    constexpr int GROUPS = COUT / COUT_BLK;

    const int bx = blockIdx.x * TILE;
    const int by = blockIdx.y * TILE;
    const int cg = blockIdx.z % GROUPS;
    const int b  = blockIdx.z / GROUPS;
    const int co0 = cg * COUT_BLK;

    __shared__ float  s_in[CIN_BLK][TILE + 2][PITCH];
    __shared__ float2 s_w2[CIN_BLK][COUT_BLK][9];     // duplicated (w,w)

    const int tx = threadIdx.x;
    const int ty = threadIdx.y;
    const int tid = ty * 16 + tx;

    u64 acc[COUT_BLK][2];   // [cout][py], each packs out cols (2tx, 2tx+1)
#pragma unroll
    for (int c = 0; c < COUT_BLK; c++) { acc[c][0] = 0ull; acc[c][1] = 0ull; }

    for (int ci0 = 0; ci0 < CIN; ci0 += CIN_BLK) {
        __syncthreads();
        // load input chunk (with zero padding)
        constexpr int LOAD_N = CIN_BLK * (TILE + 2) * (TILE + 2);
#pragma unroll 4
        for (int idx = tid; idx < LOAD_N; idx += 256) {
            int ci = idx / ((TILE + 2) * (TILE + 2));
            int r  = idx % ((TILE + 2) * (TILE + 2));
            int yy = r / (TILE + 2);
            int xx = r % (TILE + 2);
            int gy = by + yy - 1;
            int gx = bx + xx - 1;
            float v = 0.f;
            if (gy >= 0 && gy < H && gx >= 0 && gx < W)
                v = in[((size_t)(b * CIN + ci0 + ci) * H + gy) * W + gx];
            s_in[ci][yy][xx] = v;
        }
        // load weight chunk, duplicated into both lanes
        constexpr int WLOAD_N = COUT_BLK * CIN_BLK * 9;
        for (int idx = tid; idx < WLOAD_N; idx += 256) {
            int co = idx / (CIN_BLK * 9);
            int r  = idx % (CIN_BLK * 9);
            int ci = r / 9;
            int t  = r % 9;
            float w = wgt[((co0 + co) * CIN + ci0 + ci) * 9 + t];
            s_w2[ci][co][t] = make_float2(w, w);
        }
        __syncthreads();

#pragma unroll 1
        for (int ci = 0; ci < CIN_BLK; ci++) {
            // input pairs: P[row][kx] = (in[row][2tx+kx], in[row][2tx+kx+1])
            u64 P[4][3];
#pragma unroll
            for (int r = 0; r < 4; r++) {
                float2 a = *(const float2*)&s_in[ci][2 * ty + r][2 * tx];
                float2 c = *(const float2*)&s_in[ci][2 * ty + r][2 * tx + 2];
                P[r][0] = as_u64(a);
                P[r][2] = as_u64(c);
                P[r][1] = pack2(a.y, c.x);
            }
#pragma unroll
            for (int co = 0; co < COUT_BLK; co++) {
#pragma unroll
                for (int ky = 0; ky < 3; ky++) {
#pragma unroll
                    for (int kx = 0; kx < 3; kx++) {
                        u64 w = *(const u64*)&s_w2[ci][co][ky * 3 + kx];
                        fma2(acc[co][0], P[ky][kx],     w);
                        fma2(acc[co][1], P[ky + 1][kx], w);
                    }
                }
            }
        }
    }

#pragma unroll
    for (int co = 0; co < COUT_BLK; co++) {
        float bv = bias[co0 + co];
#pragma unroll
        for (int py = 0; py < 2; py++) {
            float2 a = unpack2(acc[co][py]);
            float v0 = a.x + bv;
            float v1 = a.y + bv;
            if (ACT == 1) { v0 = fmaxf(v0, 0.f); v1 = fmaxf(v1, 0.f); }
            if (ACT == 2) { v0 = tanhf(v0); v1 = tanhf(v1); }
            int oy = by + 2 * ty + py;
            int ox = bx + 2 * tx;
            *(float2*)&out[((size_t)(b * COUT + co0 + co) * H + oy) * W + ox]
                = make_float2(v0, v1);
        }
    }
}

// ---------------------------------------------------------------------------
// MaxPool 2x2 stride 2
// ---------------------------------------------------------------------------
__global__ void pool2_kernel(const float* __restrict__ in, float* __restrict__ out,
                             int total, int Hout, int Wout)
{
    int idx = blockIdx.x * blockDim.x + threadIdx.x;
    if (idx >= total) return;
    int wo = idx % Wout;
    int ho = (idx / Wout) % Hout;
    int c  = idx / (Wout * Hout);
    int Win = 2 * Wout;
    const float* p = in + ((size_t)c * (2 * Hout) + 2 * ho) * Win + 2 * wo;
    float m0 = fmaxf(p[0], p[1]);
    float m1 = fmaxf(p[Win], p[Win + 1]);
    out[idx] = fmaxf(m0, m1);
}

// ---------------------------------------------------------------------------
// Bilinear upsample x2 (half-pixel, edge clamp == jax.image.resize bilinear)
// ---------------------------------------------------------------------------
__global__ void up2_kernel(const float* __restrict__ in, float* __restrict__ out,
                           int total, int Hin, int Win)
{
    int idx = blockIdx.x * blockDim.x + threadIdx.x;
    if (idx >= total) return;
    int Hout = 2 * Hin, Wout = 2 * Win;
    int ox = idx % Wout;
    int oy = (idx / Wout) % Hout;
    int c  = idx / (Wout * Hout);

    float fy = (oy + 0.5f) * 0.5f - 0.5f;
    float fx = (ox + 0.5f) * 0.5f - 0.5f;
    int y0 = (int)floorf(fy);
    int x0 = (int)floorf(fx);
    float wy = fy - (float)y0;
    float wx = fx - (float)x0;
    int y0c = max(y0, 0), y1c = min(y0 + 1, Hin - 1);
    int x0c = max(x0, 0), x1c = min(x0 + 1, Win - 1);

    const float* base = in + (size_t)c * Hin * Win;
    float v00 = base[y0c * Win + x0c];
    float v01 = base[y0c * Win + x1c];
    float v10 = base[y1c * Win + x0c];
    float v11 = base[y1c * Win + x1c];
    out[idx] = (1.f - wy) * ((1.f - wx) * v00 + wx * v01)
             +        wy  * ((1.f - wx) * v10 + wx * v11);
}

// ---------------------------------------------------------------------------
// deformed = base_grid + flow^T * temp    ([B,H,W,2], x then y)
// ---------------------------------------------------------------------------
__global__ void deform_kernel(const float* __restrict__ flow,
                              const float* __restrict__ temp,
                              float* __restrict__ def)
{
    int idx = blockIdx.x * blockDim.x + threadIdx.x;
    int total = BATCH * IMG_H * IMG_W;
    if (idx >= total) return;
    int w = idx % IMG_W;
    int h = (idx / IMG_W) % IMG_H;
    int b = idx / (IMG_W * IMG_H);
    float gx = -1.0f + 2.0f * (float)w / (float)(IMG_W - 1);
    float gy = -1.0f + 2.0f * (float)h / (float)(IMG_H - 1);
    float t = temp[0];
    float fx = flow[((size_t)(b * 2 + 0) * IMG_H + h) * IMG_W + w];
    float fy = flow[((size_t)(b * 2 + 1) * IMG_H + h) * IMG_W + w];
    def[(size_t)idx * 2 + 0] = gx + fx * t;
    def[(size_t)idx * 2 + 1] = gy + fy * t;
}

// ---------------------------------------------------------------------------
// Patch extraction: grid_sample bilinear, zeros padding, align_corners=False
// out: [B, N=256, C=3, 64, 64]
// ---------------------------------------------------------------------------
__global__ void patches_kernel(const float* __restrict__ x,
                               const float* __restrict__ def,
                               float* __restrict__ out)
{
    int bn = blockIdx.x;            // 0..1023
    int b = bn >> 8;
    int n = bn & 255;
    int hy = n >> 4;
    int wx = n & 15;
    const float* dptr = def + (((size_t)(b * IMG_H + hy * STRIDE_) * IMG_W) + wx * STRIDE_) * 2;
    float cx = dptr[0];
    float cy = dptr[1];

    for (int p = threadIdx.x; p < PATCH * PATCH; p += blockDim.x) {
        int i = p >> 6;
        int j = p & 63;
        float pxv = -1.0f + 2.0f * (float)j / (float)(PATCH - 1);
        float pyv = -1.0f + 2.0f * (float)i / (float)(PATCH - 1);
        float gx = cx + pxv * ((float)PATCH / (float)IMG_W);
        float gy = cy + pyv * ((float)PATCH / (float)IMG_H);
        float ix = ((gx + 1.0f) * (float)IMG_W - 1.0f) * 0.5f;
        float iy = ((gy + 1.0f) * (float)IMG_H - 1.0f) * 0.5f;
        float x0f = floorf(ix), y0f = floorf(iy);
        float wx1 = ix - x0f, wy1 = iy - y0f;
        int x0 = (int)x0f, y0 = (int)y0f;
        int x1 = x0 + 1, y1 = y0 + 1;
        bool vx0 = (x0 >= 0) & (x0 <= IMG_W - 1);
        bool vx1 = (x1 >= 0) & (x1 <= IMG_W - 1);
        bool vy0 = (y0 >= 0) & (y0 <= IMG_H - 1);
        bool vy1 = (y1 >= 0) & (y1 <= IMG_H - 1);
        int x0c = min(max(x0, 0), IMG_W - 1);
        int x1c = min(max(x1, 0), IMG_W - 1);
        int y0c = min(max(y0, 0), IMG_H - 1);
        int y1c = min(max(y1, 0), IMG_H - 1);
        float w00 = (1.f - wx1) * (1.f - wy1) * (float)(vx0 && vy0);
        float w10 = wx1 * (1.f - wy1) * (float)(vx1 && vy0);
        float w01 = (1.f - wx1) * wy1 * (float)(vx0 && vy1);
        float w11 = wx1 * wy1 * (float)(vx1 && vy1);

#pragma unroll
        for (int c = 0; c < 3; c++) {
            const float* img = x + (size_t)(b * 3 + c) * IMG_H * IMG_W;
            float v = img[y0c * IMG_W + x0c] * w00
                    + img[y0c * IMG_W + x1c] * w10
                    + img[y1c * IMG_W + x0c] * w01
                    + img[y1c * IMG_W + x1c] * w11;
            out[((size_t)(bn)*3 + c) * (PATCH * PATCH) + p] = v;
        }
    }
}

// ---------------------------------------------------------------------------
// Launch
// ---------------------------------------------------------------------------
extern "C" void kernel_launch(void* const* d_in, const int* in_sizes, int n_in,
                              void* d_out, int out_size)
{
    const float* x  = (const float*)d_in[0];
    const float* w0 = (const float*)d_in[1];  const float* b0 = (const float*)d_in[2];
    const float* w1 = (const float*)d_in[3];  const float* b1 = (const float*)d_in[4];
    const float* w2 = (const float*)d_in[5];  const float* b2 = (const float*)d_in[6];
    const float* w3 = (const float*)d_in[7];  const float* b3 = (const float*)d_in[8];
    const float* w4 = (const float*)d_in[9];  const float* b4 = (const float*)d_in[10];
    const float* w5 = (const float*)d_in[11]; const float* b5 = (const float*)d_in[12];
    const float* w6 = (const float*)d_in[13]; const float* b6 = (const float*)d_in[14];
    const float* w7 = (const float*)d_in[15]; const float* b7 = (const float*)d_in[16];
    const float* temp = (const float*)d_in[17];

    float* out     = (float*)d_out;
    float* patches = out;                                  // [4,256,3,64,64]
    float* flow    = out + PATCHES_ELEMS;                  // [4,2,512,512]
    float* def     = out + PATCHES_ELEMS + FLOW_ELEMS;     // [4,512,512,2]

    float* A;  cudaGetSymbolAddress((void**)&A, g_bufA);
    float* Bb; cudaGetSymbolAddress((void**)&Bb, g_bufB);

    dim3 blk(16, 16);

    // conv0: 3->32 @512, relu                 (x -> A)   groups=4
    conv3x3_kernel<3, 32, 3, 8, 1><<<dim3(16, 16, BATCH * 4), blk>>>(x, w0, b0, A, 512, 512);
    // conv1: 32->32 @512, relu                (A -> B)   groups=4
    conv3x3_kernel<32, 32, 8, 8, 1><<<dim3(16, 16, BATCH * 4), blk>>>(A, w1, b1, Bb, 512, 512);
    // pool: 512->256                          (B -> A)
    {
        int total = BATCH * 32 * 256 * 256;
        pool2_kernel<<<(total + 255) / 256, 256>>>(Bb, A, total, 256, 256);
    }
    // conv2: 32->64 @256, relu                (A -> B)   groups=8
    conv3x3_kernel<32, 64, 8, 8, 1><<<dim3(8, 8, BATCH * 8), blk>>>(A, w2, b2, Bb, 256, 256);
    // conv3: 64->64 @256, relu                (B -> A)   groups=8
    conv3x3_kernel<64, 64, 8, 8, 1><<<dim3(8, 8, BATCH * 8), blk>>>(Bb, w3, b3, A, 256, 256);
    // pool: 256->128                          (A -> B)
    {
        int total = BATCH * 64 * 128 * 128;
        pool2_kernel<<<(total + 255) / 256, 256>>>(A, Bb, total, 128, 128);
    }
    // up: 128->256                            (B -> A)
    {
        int total = BATCH * 64 * 256 * 256;
        up2_kernel<<<(total + 255) / 256, 256>>>(Bb, A, total, 128, 128);
    }
    // conv4: 64->64 @256, relu                (A -> B)   groups=8
    conv3x3_kernel<64, 64, 8, 8, 1><<<dim3(8, 8, BATCH * 8), blk>>>(A, w4, b4, Bb, 256, 256);
    // conv5: 64->32 @256, relu                (B -> A)   groups=4
    conv3x3_kernel<64, 32, 8, 8, 1><<<dim3(8, 8, BATCH * 4), blk>>>(Bb, w5, b5, A, 256, 256);
    // up: 256->512                            (A -> B)
    {
        int total = BATCH * 32 * 512 * 512;
        up2_kernel<<<(total + 255) / 256, 256>>>(A, Bb, total, 256, 256);
    }
    // conv6: 32->32 @512, relu                (B -> A)   groups=4
    conv3x3_kernel<32, 32, 8, 8, 1><<<dim3(16, 16, BATCH * 4), blk>>>(Bb, w6, b6, A, 512, 512);
    // conv7: 32->2 @512, tanh                 (A -> flow) groups=1
    conv3x3_kernel<32, 2, 8, 2, 2><<<dim3(16, 16, BATCH * 1), blk>>>(A, w7, b7, flow, 512, 512);

    // deformed grid
    {
        int total = BATCH * IMG_H * IMG_W;
        deform_kernel<<<(total + 255) / 256, 256>>>(flow, temp, def);
    }
    // patches
    patches_kernel<<<dim3(BATCH * NPATCH), 256>>>(x, def, patches);
}

// round 6
// speedup vs baseline: 1.1301x; 1.1301x over previous
#include <cuda_runtime.h>
#include <math.h>

// ---------------------------------------------------------------------------
// Problem constants
// ---------------------------------------------------------------------------
#define BATCH 4
#define IMG_H 512
#define IMG_W 512
#define PATCH 64
#define STRIDE_ 32
#define NPATCH 256            // (512/32)^2
#define PATCHES_ELEMS (BATCH * NPATCH * 3 * PATCH * PATCH)   // 12,582,912
#define FLOW_ELEMS    (BATCH * 2 * IMG_H * IMG_W)            //  2,097,152
#define DEF_ELEMS     (BATCH * IMG_H * IMG_W * 2)            //  2,097,152

// Scratch ping-pong buffers (device globals: allocation-free scratch).
__device__ float g_bufA[33554432];
__device__ float g_bufB[33554432];

// ---------------------------------------------------------------------------
// cp.async helpers
// ---------------------------------------------------------------------------
__device__ __forceinline__ void cp_async4(void* smem_dst, const void* gptr) {
    unsigned sa = (unsigned)__cvta_generic_to_shared(smem_dst);
    asm volatile("cp.async.ca.shared.global [%0], [%1], 4;" :: "r"(sa), "l"(gptr));
}
__device__ __forceinline__ void cp_commit() {
    asm volatile("cp.async.commit_group;");
}
__device__ __forceinline__ void cp_wait0() {
    asm volatile("cp.async.wait_group 0;");
}

// ---------------------------------------------------------------------------
// Direct 3x3 conv, pad=1, ReLU/tanh; double-buffered cp.async pipeline.
// Block = 16x16 threads; each thread: 2x2 pixels x COUT_BLK output channels.
// Input streamed through smem in CIN_BLK-channel chunks; chunk c+1 is
// prefetched via cp.async while chunk c computes.
// ACT: 0=none, 1=relu, 2=tanh
// ---------------------------------------------------------------------------
template <int CIN, int CIN_BLK, int COUT_BLK>
__device__ __forceinline__ void load_chunk(
    float (*s_in)[34][36], float (*s_w)[COUT_BLK][9],
    const float* __restrict__ in, const float* __restrict__ wgt,
    int b, int co0, int ci0, int bx, int by, int H, int W, int tid)
{
    constexpr int ROWS = 34;
    constexpr int LOAD_N = CIN_BLK * ROWS * ROWS;
    for (int idx = tid; idx < LOAD_N; idx += 256) {
        int ci = idx / (ROWS * ROWS);
        int r  = idx % (ROWS * ROWS);
        int yy = r / ROWS;
        int xx = r % ROWS;
        int gy = by + yy - 1;
        int gx = bx + xx - 1;
        float* dst = &s_in[ci][yy][xx];
        if (gy >= 0 && gy < H && gx >= 0 && gx < W)
            cp_async4(dst, &in[((size_t)(b * CIN + ci0 + ci) * H + gy) * W + gx]);
        else
            *dst = 0.f;
    }
    constexpr int WN = CIN_BLK * COUT_BLK * 9;
    for (int idx = tid; idx < WN; idx += 256) {
        int co = idx / (CIN_BLK * 9);
        int r  = idx % (CIN_BLK * 9);
        int ci = r / 9;
        int t  = r % 9;
        cp_async4(&s_w[ci][co][t], &wgt[((size_t)(co0 + co) * CIN + ci0 + ci) * 9 + t]);
    }
    cp_commit();
}

template <int CIN, int COUT, int CIN_BLK, int COUT_BLK, int ACT>
__global__ void __launch_bounds__(256, 3)
conv3x3_kernel(const float* __restrict__ in, const float* __restrict__ wgt,
               const float* __restrict__ bias, float* __restrict__ out,
               int H, int W)
{
    constexpr int TILE = 32;
    constexpr int ROWS = 34;
    constexpr int PITCH = 36;          // even pitch -> 8B-aligned float2 loads
    constexpr int GROUPS = COUT / COUT_BLK;
    constexpr int NCHUNK = CIN / CIN_BLK;

    const int bx = blockIdx.x * TILE;
    const int by = blockIdx.y * TILE;
    const int cg = blockIdx.z % GROUPS;
    const int b  = blockIdx.z / GROUPS;
    const int co0 = cg * COUT_BLK;

    __shared__ float s_in[2][CIN_BLK][ROWS][PITCH];
    __shared__ float s_w[2][CIN_BLK][COUT_BLK][9];

    const int tx = threadIdx.x;
    const int ty = threadIdx.y;
    const int tid = ty * 16 + tx;

    float acc[COUT_BLK][2][2];
#pragma unroll
    for (int c = 0; c < COUT_BLK; c++) {
        acc[c][0][0] = 0.f; acc[c][0][1] = 0.f;
        acc[c][1][0] = 0.f; acc[c][1][1] = 0.f;
    }

    // prologue: prefetch chunk 0
    load_chunk<CIN, CIN_BLK, COUT_BLK>(s_in[0], s_w[0], in, wgt,
                                       b, co0, 0, bx, by, H, W, tid);

#pragma unroll 1
    for (int c = 0; c < NCHUNK; c++) {
        cp_wait0();
        __syncthreads();
        if (c + 1 < NCHUNK)
            load_chunk<CIN, CIN_BLK, COUT_BLK>(s_in[(c + 1) & 1], s_w[(c + 1) & 1],
                                               in, wgt, b, co0, (c + 1) * CIN_BLK,
                                               bx, by, H, W, tid);
        const int bsel = c & 1;
#pragma unroll 1
        for (int ci = 0; ci < CIN_BLK; ci++) {
            float iv[4][4];
#pragma unroll
            for (int r = 0; r < 4; r++) {
                float2 a  = *(const float2*)&s_in[bsel][ci][2 * ty + r][2 * tx];
                float2 cc = *(const float2*)&s_in[bsel][ci][2 * ty + r][2 * tx + 2];
                iv[r][0] = a.x; iv[r][1] = a.y; iv[r][2] = cc.x; iv[r][3] = cc.y;
            }
#pragma unroll
            for (int co = 0; co < COUT_BLK; co++) {
#pragma unroll
                for (int ky = 0; ky < 3; ky++) {
#pragma unroll
                    for (int kx = 0; kx < 3; kx++) {
                        float wv = s_w[bsel][ci][co][ky * 3 + kx];
                        acc[co][0][0] = fmaf(iv[ky][kx],         wv, acc[co][0][0]);
                        acc[co][0][1] = fmaf(iv[ky][kx + 1],     wv, acc[co][0][1]);
                        acc[co][1][0] = fmaf(iv[ky + 1][kx],     wv, acc[co][1][0]);
                        acc[co][1][1] = fmaf(iv[ky + 1][kx + 1], wv, acc[co][1][1]);
                    }
                }
            }
        }
        __syncthreads();
    }

#pragma unroll
    for (int co = 0; co < COUT_BLK; co++) {
        float bv = bias[co0 + co];
#pragma unroll
        for (int py = 0; py < 2; py++) {
            float v0 = acc[co][py][0] + bv;
            float v1 = acc[co][py][1] + bv;
            if (ACT == 1) { v0 = fmaxf(v0, 0.f); v1 = fmaxf(v1, 0.f); }
            if (ACT == 2) { v0 = tanhf(v0); v1 = tanhf(v1); }
            int oy = by + 2 * ty + py;
            int ox = bx + 2 * tx;
            *(float2*)&out[((size_t)(b * COUT + co0 + co) * H + oy) * W + ox]
                = make_float2(v0, v1);
        }
    }
}

// ---------------------------------------------------------------------------
// MaxPool 2x2 stride 2
// ---------------------------------------------------------------------------
__global__ void pool2_kernel(const float* __restrict__ in, float* __restrict__ out,
                             int total, int Hout, int Wout)
{
    int idx = blockIdx.x * blockDim.x + threadIdx.x;
    if (idx >= total) return;
    int wo = idx % Wout;
    int ho = (idx / Wout) % Hout;
    int c  = idx / (Wout * Hout);
    int Win = 2 * Wout;
    const float* p = in + ((size_t)c * (2 * Hout) + 2 * ho) * Win + 2 * wo;
    float m0 = fmaxf(p[0], p[1]);
    float m1 = fmaxf(p[Win], p[Win + 1]);
    out[idx] = fmaxf(m0, m1);
}

// ---------------------------------------------------------------------------
// Bilinear upsample x2 (half-pixel, edge clamp == jax.image.resize bilinear)
// ---------------------------------------------------------------------------
__global__ void up2_kernel(const float* __restrict__ in, float* __restrict__ out,
                           int total, int Hin, int Win)
{
    int idx = blockIdx.x * blockDim.x + threadIdx.x;
    if (idx >= total) return;
    int Hout = 2 * Hin, Wout = 2 * Win;
    int ox = idx % Wout;
    int oy = (idx / Wout) % Hout;
    int c  = idx / (Wout * Hout);

    float fy = (oy + 0.5f) * 0.5f - 0.5f;
    float fx = (ox + 0.5f) * 0.5f - 0.5f;
    int y0 = (int)floorf(fy);
    int x0 = (int)floorf(fx);
    float wy = fy - (float)y0;
    float wx = fx - (float)x0;
    int y0c = max(y0, 0), y1c = min(y0 + 1, Hin - 1);
    int x0c = max(x0, 0), x1c = min(x0 + 1, Win - 1);

    const float* base = in + (size_t)c * Hin * Win;
    float v00 = base[y0c * Win + x0c];
    float v01 = base[y0c * Win + x1c];
    float v10 = base[y1c * Win + x0c];
    float v11 = base[y1c * Win + x1c];
    out[idx] = (1.f - wy) * ((1.f - wx) * v00 + wx * v01)
             +        wy  * ((1.f - wx) * v10 + wx * v11);
}

// ---------------------------------------------------------------------------
// deformed = base_grid + flow^T * temp    ([B,H,W,2], x then y)
// ---------------------------------------------------------------------------
__global__ void deform_kernel(const float* __restrict__ flow,
                              const float* __restrict__ temp,
                              float* __restrict__ def)
{
    int idx = blockIdx.x * blockDim.x + threadIdx.x;
    int total = BATCH * IMG_H * IMG_W;
    if (idx >= total) return;
    int w = idx % IMG_W;
    int h = (idx / IMG_W) % IMG_H;
    int b = idx / (IMG_W * IMG_H);
    float gx = -1.0f + 2.0f * (float)w / (float)(IMG_W - 1);
    float gy = -1.0f + 2.0f * (float)h / (float)(IMG_H - 1);
    float t = temp[0];
    float fx = flow[((size_t)(b * 2 + 0) * IMG_H + h) * IMG_W + w];
    float fy = flow[((size_t)(b * 2 + 1) * IMG_H + h) * IMG_W + w];
    def[(size_t)idx * 2 + 0] = gx + fx * t;
    def[(size_t)idx * 2 + 1] = gy + fy * t;
}

// ---------------------------------------------------------------------------
// Patch extraction: grid_sample bilinear, zeros padding, align_corners=False
// out: [B, N=256, C=3, 64, 64]
// ---------------------------------------------------------------------------
__global__ void patches_kernel(const float* __restrict__ x,
                               const float* __restrict__ def,
                               float* __restrict__ out)
{
    int bn = blockIdx.x;            // 0..1023
    int b = bn >> 8;
    int n = bn & 255;
    int hy = n >> 4;
    int wx = n & 15;
    const float* dptr = def + (((size_t)(b * IMG_H + hy * STRIDE_) * IMG_W) + wx * STRIDE_) * 2;
    float cx = dptr[0];
    float cy = dptr[1];

    for (int p = threadIdx.x; p < PATCH * PATCH; p += blockDim.x) {
        int i = p >> 6;
        int j = p & 63;
        float pxv = -1.0f + 2.0f * (float)j / (float)(PATCH - 1);
        float pyv = -1.0f + 2.0f * (float)i / (float)(PATCH - 1);
        float gx = cx + pxv * ((float)PATCH / (float)IMG_W);
        float gy = cy + pyv * ((float)PATCH / (float)IMG_H);
        float ix = ((gx + 1.0f) * (float)IMG_W - 1.0f) * 0.5f;
        float iy = ((gy + 1.0f) * (float)IMG_H - 1.0f) * 0.5f;
        float x0f = floorf(ix), y0f = floorf(iy);
        float wx1 = ix - x0f, wy1 = iy - y0f;
        int x0 = (int)x0f, y0 = (int)y0f;
        int x1 = x0 + 1, y1 = y0 + 1;
        bool vx0 = (x0 >= 0) & (x0 <= IMG_W - 1);
        bool vx1 = (x1 >= 0) & (x1 <= IMG_W - 1);
        bool vy0 = (y0 >= 0) & (y0 <= IMG_H - 1);
        bool vy1 = (y1 >= 0) & (y1 <= IMG_H - 1);
        int x0c = min(max(x0, 0), IMG_W - 1);
        int x1c = min(max(x1, 0), IMG_W - 1);
        int y0c = min(max(y0, 0), IMG_H - 1);
        int y1c = min(max(y1, 0), IMG_H - 1);
        float w00 = (1.f - wx1) * (1.f - wy1) * (float)(vx0 && vy0);
        float w10 = wx1 * (1.f - wy1) * (float)(vx1 && vy0);
        float w01 = (1.f - wx1) * wy1 * (float)(vx0 && vy1);
        float w11 = wx1 * wy1 * (float)(vx1 && vy1);

#pragma unroll
        for (int c = 0; c < 3; c++) {
            const float* img = x + (size_t)(b * 3 + c) * IMG_H * IMG_W;
            float v = img[y0c * IMG_W + x0c] * w00
                    + img[y0c * IMG_W + x1c] * w10
                    + img[y1c * IMG_W + x0c] * w01
                    + img[y1c * IMG_W + x1c] * w11;
            out[((size_t)(bn)*3 + c) * (PATCH * PATCH) + p] = v;
        }
    }
}

// ---------------------------------------------------------------------------
// Launch
// ---------------------------------------------------------------------------
extern "C" void kernel_launch(void* const* d_in, const int* in_sizes, int n_in,
                              void* d_out, int out_size)
{
    const float* x  = (const float*)d_in[0];
    const float* w0 = (const float*)d_in[1];  const float* b0 = (const float*)d_in[2];
    const float* w1 = (const float*)d_in[3];  const float* b1 = (const float*)d_in[4];
    const float* w2 = (const float*)d_in[5];  const float* b2 = (const float*)d_in[6];
    const float* w3 = (const float*)d_in[7];  const float* b3 = (const float*)d_in[8];
    const float* w4 = (const float*)d_in[9];  const float* b4 = (const float*)d_in[10];
    const float* w5 = (const float*)d_in[11]; const float* b5 = (const float*)d_in[12];
    const float* w6 = (const float*)d_in[13]; const float* b6 = (const float*)d_in[14];
    const float* w7 = (const float*)d_in[15]; const float* b7 = (const float*)d_in[16];
    const float* temp = (const float*)d_in[17];

    float* out     = (float*)d_out;
    float* patches = out;                                  // [4,256,3,64,64]
    float* flow    = out + PATCHES_ELEMS;                  // [4,2,512,512]
    float* def     = out + PATCHES_ELEMS + FLOW_ELEMS;     // [4,512,512,2]

    float* A;  cudaGetSymbolAddress((void**)&A, g_bufA);
    float* Bb; cudaGetSymbolAddress((void**)&Bb, g_bufB);

    dim3 blk(16, 16);

    // conv0: 3->32 @512, relu                 (x -> A)   groups=4, 1 chunk
    conv3x3_kernel<3, 32, 3, 8, 1><<<dim3(16, 16, BATCH * 4), blk>>>(x, w0, b0, A, 512, 512);
    // conv1: 32->32 @512, relu                (A -> B)   groups=4
    conv3x3_kernel<32, 32, 4, 8, 1><<<dim3(16, 16, BATCH * 4), blk>>>(A, w1, b1, Bb, 512, 512);
    // pool: 512->256                          (B -> A)
    {
        int total = BATCH * 32 * 256 * 256;
        pool2_kernel<<<(total + 255) / 256, 256>>>(Bb, A, total, 256, 256);
    }
    // conv2: 32->64 @256, relu                (A -> B)   groups=8
    conv3x3_kernel<32, 64, 4, 8, 1><<<dim3(8, 8, BATCH * 8), blk>>>(A, w2, b2, Bb, 256, 256);
    // conv3: 64->64 @256, relu                (B -> A)   groups=8
    conv3x3_kernel<64, 64, 4, 8, 1><<<dim3(8, 8, BATCH * 8), blk>>>(Bb, w3, b3, A, 256, 256);
    // pool: 256->128                          (A -> B)
    {
        int total = BATCH * 64 * 128 * 128;
        pool2_kernel<<<(total + 255) / 256, 256>>>(A, Bb, total, 128, 128);
    }
    // up: 128->256                            (B -> A)
    {
        int total = BATCH * 64 * 256 * 256;
        up2_kernel<<<(total + 255) / 256, 256>>>(Bb, A, total, 128, 128);
    }
    // conv4: 64->64 @256, relu                (A -> B)   groups=8
    conv3x3_kernel<64, 64, 4, 8, 1><<<dim3(8, 8, BATCH * 8), blk>>>(A, w4, b4, Bb, 256, 256);
    // conv5: 64->32 @256, relu                (B -> A)   groups=4
    conv3x3_kernel<64, 32, 4, 8, 1><<<dim3(8, 8, BATCH * 4), blk>>>(Bb, w5, b5, A, 256, 256);
    // up: 256->512                            (A -> B)
    {
        int total = BATCH * 32 * 512 * 512;
        up2_kernel<<<(total + 255) / 256, 256>>>(A, Bb, total, 256, 256);
    }
    // conv6: 32->32 @512, relu                (B -> A)   groups=4
    conv3x3_kernel<32, 32, 4, 8, 1><<<dim3(16, 16, BATCH * 4), blk>>>(Bb, w6, b6, A, 512, 512);
    // conv7: 32->2 @512, tanh                 (A -> flow) groups=1
    conv3x3_kernel<32, 2, 4, 2, 2><<<dim3(16, 16, BATCH * 1), blk>>>(A, w7, b7, flow, 512, 512);

    // deformed grid
    {
        int total = BATCH * IMG_H * IMG_W;
        deform_kernel<<<(total + 255) / 256, 256>>>(flow, temp, def);
    }
    // patches
    patches_kernel<<<dim3(BATCH * NPATCH), 256>>>(x, def, patches);
}

// round 7
// speedup vs baseline: 1.9868x; 1.7581x over previous
#include <cuda_runtime.h>
#include <cuda_bf16.h>
#include <math.h>

// ---------------------------------------------------------------------------
// Problem constants
// ---------------------------------------------------------------------------
#define BATCH 4
#define IMG_H 512
#define IMG_W 512
#define PATCH 64
#define STRIDE_ 32
#define NPATCH 256
#define PATCHES_ELEMS (BATCH * NPATCH * 3 * PATCH * PATCH)   // 12,582,912
#define FLOW_ELEMS    (BATCH * 2 * IMG_H * IMG_W)            //  2,097,152
#define DEF_ELEMS     (BATCH * IMG_H * IMG_W * 2)            //  2,097,152

// Scratch (device globals: allocation-free scratch).
__device__ float g_bufA[33554432];
__device__ float g_bufB[33554432];

// Preconverted weights (bf16 hi/lo, swizzled). Total elems per plane = 138240.
#define WSCRATCH 138240
__device__ __align__(16) __nv_bfloat16 g_wh[WSCRATCH];
__device__ __align__(16) __nv_bfloat16 g_wl[WSCRATCH];

// ---------------------------------------------------------------------------
// helpers
// ---------------------------------------------------------------------------
__device__ __forceinline__ void cp_async16(void* smem_dst, const void* gptr) {
    unsigned sa = (unsigned)__cvta_generic_to_shared(smem_dst);
    asm volatile("cp.async.cg.shared.global [%0], [%1], 16;" :: "r"(sa), "l"(gptr));
}
__device__ __forceinline__ void cp_commit() { asm volatile("cp.async.commit_group;"); }
__device__ __forceinline__ void cp_wait0()  { asm volatile("cp.async.wait_group 0;"); }

__device__ __forceinline__ void mma16816(float* c, const unsigned* a, unsigned b0, unsigned b1) {
    asm volatile(
        "mma.sync.aligned.m16n8k16.row.col.f32.bf16.bf16.f32 "
        "{%0,%1,%2,%3}, {%4,%5,%6,%7}, {%8,%9}, {%0,%1,%2,%3};"
        : "+f"(c[0]), "+f"(c[1]), "+f"(c[2]), "+f"(c[3])
        : "r"(a[0]), "r"(a[1]), "r"(a[2]), "r"(a[3]), "r"(b0), "r"(b1));
}
__device__ __forceinline__ unsigned lds32(const __nv_bfloat16* p) {
    return *(const unsigned*)p;
}

// ---------------------------------------------------------------------------
// Weight preconversion: fp32 [COUT][CIN][3][3] ->
// bf16 hi/lo planes laid out [grp][cinblk][tap][co(local,COUTP)][ci slot 16],
// slot = (ci + 2*co) & 15 (swizzle), zero-padded for cin/cout padding.
// ---------------------------------------------------------------------------
__global__ void wconv_kernel(const float* __restrict__ w,
                             __nv_bfloat16* __restrict__ dh,
                             __nv_bfloat16* __restrict__ dl,
                             int COUT, int CIN, int COUTP, int GRPS, int CBLKS)
{
    int total = GRPS * CBLKS * 9 * COUTP * 16;
    int idx = blockIdx.x * blockDim.x + threadIdx.x;
    if (idx >= total) return;
    int slot = idx & 15;
    int t = idx >> 4;
    int co = t % COUTP;  t /= COUTP;
    int tap = t % 9;     t /= 9;
    int cb = t % CBLKS;
    int grp = t / CBLKS;
    int ci = (slot - 2 * co) & 15;
    int co_g = grp * COUTP + co;
    int ci_g = cb * 16 + ci;
    float v = 0.f;
    if (co_g < COUT && ci_g < CIN)
        v = w[((size_t)co_g * CIN + ci_g) * 9 + tap];
    __nv_bfloat16 h = __float2bfloat16(v);
    dh[idx] = h;
    dl[idx] = __float2bfloat16(v - __bfloat162float(h));
}

// ---------------------------------------------------------------------------
// Implicit-GEMM 3x3 conv via mma.sync bf16 (3-term hi/lo split = fp32-class).
// CTA: 256 threads (8 warps). Output tile: 64 wide x 8 tall x COUTP couts.
// warp w handles output row (by+w); 8 n-tiles of 8 pixels each.
// smem input: [10 rows][68 cols][16 ci] bf16, hi & lo planes, ci-swizzled.
// ACT: 1=relu, 2=tanh
// ---------------------------------------------------------------------------
template <int NCT, int ACT>
__global__ void __launch_bounds__(256, 2)
conv_mma_kernel(const float* __restrict__ in,
                const __nv_bfloat16* __restrict__ gwh,
                const __nv_bfloat16* __restrict__ gwl,
                const float* __restrict__ bias, float* __restrict__ out,
                int H, int W, int CIN, int COUT, int CBLKS, int GRPS)
{
    constexpr int COUTP = NCT * 16;
    constexpr int IN_PLANE = 10 * 68 * 16;     // 10880 bf16
    constexpr int WPL = 9 * COUTP * 16;        // weights per (grp,cb) per plane
    extern __shared__ char smraw[];
    __nv_bfloat16* s_hi = (__nv_bfloat16*)smraw;
    __nv_bfloat16* s_lo = s_hi + IN_PLANE;
    __nv_bfloat16* s_wh = s_hi + 2 * IN_PLANE;
    __nv_bfloat16* s_wl = s_wh + WPL;

    const int bx = blockIdx.x * 64;
    const int by = blockIdx.y * 8;
    const int grp = blockIdx.z % GRPS;
    const int b   = blockIdx.z / GRPS;

    const int tid  = threadIdx.x;
    const int warp = tid >> 5;
    const int lane = tid & 31;
    const int gid  = lane >> 2;   // 0..7
    const int qid  = lane & 3;    // 0..3

    float acc[NCT][8][4];
#pragma unroll
    for (int ct = 0; ct < NCT; ct++)
#pragma unroll
        for (int nt = 0; nt < 8; nt++) {
            acc[ct][nt][0] = 0.f; acc[ct][nt][1] = 0.f;
            acc[ct][nt][2] = 0.f; acc[ct][nt][3] = 0.f;
        }

    for (int cb = 0; cb < CBLKS; cb++) {
        __syncthreads();   // previous compute done before smem overwrite
        // ---- stage input chunk (fp32 -> bf16 hi/lo, swizzled, zero halo) ----
        for (int idx = tid; idx < 10 * 66 * 16; idx += 256) {
            int ci = idx & 15;
            int rc = idx >> 4;
            int col = rc % 66;
            int row = rc / 66;
            int gy = by + row - 1;
            int gx = bx + col - 1;
            int cig = cb * 16 + ci;
            float v = 0.f;
            if (gy >= 0 && gy < H && gx >= 0 && gx < W && cig < CIN)
                v = in[((size_t)(b * CIN + cig) * H + gy) * W + gx];
            __nv_bfloat16 h = __float2bfloat16(v);
            __nv_bfloat16 l = __float2bfloat16(v - __bfloat162float(h));
            int s = (row * 68 + col) * 16 + ((ci + 2 * col) & 15);
            s_hi[s] = h;
            s_lo[s] = l;
        }
        // ---- stage weights (bf16 copy, already swizzled) ----
        {
            const __nv_bfloat16* pwh = gwh + ((size_t)grp * CBLKS + cb) * WPL;
            const __nv_bfloat16* pwl = gwl + ((size_t)grp * CBLKS + cb) * WPL;
            for (int idx = tid * 8; idx < WPL; idx += 2048) {
                cp_async16(s_wh + idx, pwh + idx);
                cp_async16(s_wl + idx, pwl + idx);
            }
            cp_commit();
            cp_wait0();
        }
        __syncthreads();

        // ---- compute: 9 taps x NCT cout-tiles x 8 n-tiles ----
        int ky = 0, kx = 0;
#pragma unroll 1
        for (int tap = 0; tap < 9; tap++) {
            // A fragments (hi & lo) for each cout tile
            unsigned ah[NCT][4], al[NCT][4];
            const int wbase = tap * COUTP * 16;
#pragma unroll
            for (int ct = 0; ct < NCT; ct++) {
                int co_l = ct * 16 + gid;
                int sl0 = (2 * qid + 2 * co_l) & 15;
                int sl2 = (sl0 + 8) & 15;
                int r0 = wbase + co_l * 16;
                int r1 = wbase + (co_l + 8) * 16;
                ah[ct][0] = lds32(s_wh + r0 + sl0);
                ah[ct][1] = lds32(s_wh + r1 + sl0);
                ah[ct][2] = lds32(s_wh + r0 + sl2);
                ah[ct][3] = lds32(s_wh + r1 + sl2);
                al[ct][0] = lds32(s_wl + r0 + sl0);
                al[ct][1] = lds32(s_wl + r1 + sl0);
                al[ct][2] = lds32(s_wl + r0 + sl2);
                al[ct][3] = lds32(s_wl + r1 + sl2);
            }
            const int rowb = warp + ky;
#pragma unroll
            for (int nt = 0; nt < 8; nt++) {
                int colb = nt * 8 + gid + kx;
                int base = (rowb * 68 + colb) * 16;
                int slb0 = (2 * qid + 2 * colb) & 15;
                int slb1 = (slb0 + 8) & 15;
                unsigned bh0 = lds32(s_hi + base + slb0);
                unsigned bh1 = lds32(s_hi + base + slb1);
                unsigned bl0 = lds32(s_lo + base + slb0);
                unsigned bl1 = lds32(s_lo + base + slb1);
#pragma unroll
                for (int ct = 0; ct < NCT; ct++) {
                    mma16816(acc[ct][nt], ah[ct], bh0, bh1);
                    mma16816(acc[ct][nt], ah[ct], bl0, bl1);
                    mma16816(acc[ct][nt], al[ct], bh0, bh1);
                }
            }
            if (++kx == 3) { kx = 0; ++ky; }
        }
    }

    // ---- epilogue ----
    const int gy = by + warp;
#pragma unroll
    for (int ct = 0; ct < NCT; ct++) {
        int co0r = grp * COUTP + ct * 16 + gid;
        int co1r = co0r + 8;
        bool ok0 = co0r < COUT;
        bool ok1 = co1r < COUT;
        float bv0 = ok0 ? bias[co0r] : 0.f;
        float bv1 = ok1 ? bias[co1r] : 0.f;
#pragma unroll
        for (int nt = 0; nt < 8; nt++) {
            int gxv = bx + nt * 8 + 2 * qid;
            if (ok0) {
                float v0 = acc[ct][nt][0] + bv0;
                float v1 = acc[ct][nt][1] + bv0;
                if (ACT == 1) { v0 = fmaxf(v0, 0.f); v1 = fmaxf(v1, 0.f); }
                else          { v0 = tanhf(v0);      v1 = tanhf(v1); }
                *(float2*)&out[((size_t)(b * COUT + co0r) * H + gy) * W + gxv]
                    = make_float2(v0, v1);
            }
            if (ok1) {
                float v0 = acc[ct][nt][2] + bv1;
                float v1 = acc[ct][nt][3] + bv1;
                if (ACT == 1) { v0 = fmaxf(v0, 0.f); v1 = fmaxf(v1, 0.f); }
                else          { v0 = tanhf(v0);      v1 = tanhf(v1); }
                *(float2*)&out[((size_t)(b * COUT + co1r) * H + gy) * W + gxv]
                    = make_float2(v0, v1);
            }
        }
    }
}

// ---------------------------------------------------------------------------
// MaxPool 2x2 stride 2
// ---------------------------------------------------------------------------
__global__ void pool2_kernel(const float* __restrict__ in, float* __restrict__ out,
                             int total, int Hout, int Wout)
{
    int idx = blockIdx.x * blockDim.x + threadIdx.x;
    if (idx >= total) return;
    int wo = idx % Wout;
    int ho = (idx / Wout) % Hout;
    int c  = idx / (Wout * Hout);
    int Win = 2 * Wout;
    const float* p = in + ((size_t)c * (2 * Hout) + 2 * ho) * Win + 2 * wo;
    float m0 = fmaxf(p[0], p[1]);
    float m1 = fmaxf(p[Win], p[Win + 1]);
    out[idx] = fmaxf(m0, m1);
}

// ---------------------------------------------------------------------------
// Bilinear upsample x2 (half-pixel, edge clamp)
// ---------------------------------------------------------------------------
__global__ void up2_kernel(const float* __restrict__ in, float* __restrict__ out,
                           int total, int Hin, int Win)
{
    int idx = blockIdx.x * blockDim.x + threadIdx.x;
    if (idx >= total) return;
    int Hout = 2 * Hin, Wout = 2 * Win;
    int ox = idx % Wout;
    int oy = (idx / Wout) % Hout;
    int c  = idx / (Wout * Hout);

    float fy = (oy + 0.5f) * 0.5f - 0.5f;
    float fx = (ox + 0.5f) * 0.5f - 0.5f;
    int y0 = (int)floorf(fy);
    int x0 = (int)floorf(fx);
    float wy = fy - (float)y0;
    float wx = fx - (float)x0;
    int y0c = max(y0, 0), y1c = min(y0 + 1, Hin - 1);
    int x0c = max(x0, 0), x1c = min(x0 + 1, Win - 1);

    const float* base = in + (size_t)c * Hin * Win;
    float v00 = base[y0c * Win + x0c];
    float v01 = base[y0c * Win + x1c];
    float v10 = base[y1c * Win + x0c];
    float v11 = base[y1c * Win + x1c];
    out[idx] = (1.f - wy) * ((1.f - wx) * v00 + wx * v01)
             +        wy  * ((1.f - wx) * v10 + wx * v11);
}

// ---------------------------------------------------------------------------
// deformed = base_grid + flow^T * temp
// ---------------------------------------------------------------------------
__global__ void deform_kernel(const float* __restrict__ flow,
                              const float* __restrict__ temp,
                              float* __restrict__ def)
{
    int idx = blockIdx.x * blockDim.x + threadIdx.x;
    int total = BATCH * IMG_H * IMG_W;
    if (idx >= total) return;
    int w = idx % IMG_W;
    int h = (idx / IMG_W) % IMG_H;
    int b = idx / (IMG_W * IMG_H);
    float gx = -1.0f + 2.0f * (float)w / (float)(IMG_W - 1);
    float gy = -1.0f + 2.0f * (float)h / (float)(IMG_H - 1);
    float t = temp[0];
    float fx = flow[((size_t)(b * 2 + 0) * IMG_H + h) * IMG_W + w];
    float fy = flow[((size_t)(b * 2 + 1) * IMG_H + h) * IMG_W + w];
    def[(size_t)idx * 2 + 0] = gx + fx * t;
    def[(size_t)idx * 2 + 1] = gy + fy * t;
}

// ---------------------------------------------------------------------------
// Patch extraction (grid_sample bilinear, zeros padding)
// ---------------------------------------------------------------------------
__global__ void patches_kernel(const float* __restrict__ x,
                               const float* __restrict__ def,
                               float* __restrict__ out)
{
    int bn = blockIdx.x;
    int b = bn >> 8;
    int n = bn & 255;
    int hy = n >> 4;
    int wx = n & 15;
    const float* dptr = def + (((size_t)(b * IMG_H + hy * STRIDE_) * IMG_W) + wx * STRIDE_) * 2;
    float cx = dptr[0];
    float cy = dptr[1];

    for (int p = threadIdx.x; p < PATCH * PATCH; p += blockDim.x) {
        int i = p >> 6;
        int j = p & 63;
        float pxv = -1.0f + 2.0f * (float)j / (float)(PATCH - 1);
        float pyv = -1.0f + 2.0f * (float)i / (float)(PATCH - 1);
        float gx = cx + pxv * ((float)PATCH / (float)IMG_W);
        float gy = cy + pyv * ((float)PATCH / (float)IMG_H);
        float ix = ((gx + 1.0f) * (float)IMG_W - 1.0f) * 0.5f;
        float iy = ((gy + 1.0f) * (float)IMG_H - 1.0f) * 0.5f;
        float x0f = floorf(ix), y0f = floorf(iy);
        float wx1 = ix - x0f, wy1 = iy - y0f;
        int x0 = (int)x0f, y0 = (int)y0f;
        int x1 = x0 + 1, y1 = y0 + 1;
        bool vx0 = (x0 >= 0) & (x0 <= IMG_W - 1);
        bool vx1 = (x1 >= 0) & (x1 <= IMG_W - 1);
        bool vy0 = (y0 >= 0) & (y0 <= IMG_H - 1);
        bool vy1 = (y1 >= 0) & (y1 <= IMG_H - 1);
        int x0c = min(max(x0, 0), IMG_W - 1);
        int x1c = min(max(x1, 0), IMG_W - 1);
        int y0c = min(max(y0, 0), IMG_H - 1);
        int y1c = min(max(y1, 0), IMG_H - 1);
        float w00 = (1.f - wx1) * (1.f - wy1) * (float)(vx0 && vy0);
        float w10 = wx1 * (1.f - wy1) * (float)(vx1 && vy0);
        float w01 = (1.f - wx1) * wy1 * (float)(vx0 && vy1);
        float w11 = wx1 * wy1 * (float)(vx1 && vy1);

#pragma unroll
        for (int c = 0; c < 3; c++) {
            const float* img = x + (size_t)(b * 3 + c) * IMG_H * IMG_W;
            float v = img[y0c * IMG_W + x0c] * w00
                    + img[y0c * IMG_W + x1c] * w10
                    + img[y1c * IMG_W + x0c] * w01
                    + img[y1c * IMG_W + x1c] * w11;
            out[((size_t)(bn)*3 + c) * (PATCH * PATCH) + p] = v;
        }
    }
}

// ---------------------------------------------------------------------------
// Launch
// ---------------------------------------------------------------------------
#define SMEM_NCT2 ((2 * 10880 + 2 * 4608) * 2)   // 61952 B
#define SMEM_NCT1 ((2 * 10880 + 2 * 2304) * 2)   // 52736 B

extern "C" void kernel_launch(void* const* d_in, const int* in_sizes, int n_in,
                              void* d_out, int out_size)
{
    const float* x  = (const float*)d_in[0];
    const float* w0 = (const float*)d_in[1];  const float* b0 = (const float*)d_in[2];
    const float* w1 = (const float*)d_in[3];  const float* b1 = (const float*)d_in[4];
    const float* w2 = (const float*)d_in[5];  const float* b2 = (const float*)d_in[6];
    const float* w3 = (const float*)d_in[7];  const float* b3 = (const float*)d_in[8];
    const float* w4 = (const float*)d_in[9];  const float* b4 = (const float*)d_in[10];
    const float* w5 = (const float*)d_in[11]; const float* b5 = (const float*)d_in[12];
    const float* w6 = (const float*)d_in[13]; const float* b6 = (const float*)d_in[14];
    const float* w7 = (const float*)d_in[15]; const float* b7 = (const float*)d_in[16];
    const float* temp = (const float*)d_in[17];

    float* out     = (float*)d_out;
    float* patches = out;
    float* flow    = out + PATCHES_ELEMS;
    float* def     = out + PATCHES_ELEMS + FLOW_ELEMS;

    float* A;  cudaGetSymbolAddress((void**)&A, g_bufA);
    float* Bb; cudaGetSymbolAddress((void**)&Bb, g_bufB);
    __nv_bfloat16* WH; cudaGetSymbolAddress((void**)&WH, g_wh);
    __nv_bfloat16* WL; cudaGetSymbolAddress((void**)&WL, g_wl);

    cudaFuncSetAttribute((const void*)conv_mma_kernel<2, 1>,
                         cudaFuncAttributeMaxDynamicSharedMemorySize, SMEM_NCT2);
    cudaFuncSetAttribute((const void*)conv_mma_kernel<1, 2>,
                         cudaFuncAttributeMaxDynamicSharedMemorySize, SMEM_NCT1);

    // ---- preconvert weights (offsets per plane, elements) ----
    // L0 off=0      sz=4608  (GRPS=1, CBLKS=1, COUTP=32)
    // L1 off=4608   sz=9216  (1,2,32)
    // L2 off=13824  sz=18432 (2,2,32)
    // L3 off=32256  sz=36864 (2,4,32)
    // L4 off=69120  sz=36864 (2,4,32)
    // L5 off=105984 sz=18432 (1,4,32)
    // L6 off=124416 sz=9216  (1,2,32)
    // L7 off=133632 sz=4608  (1,2,16)
    struct { const float* w; int off, COUT, CIN, COUTP, GRPS, CBLKS; } wl[8] = {
        {w0, 0,      32,  3, 32, 1, 1},
        {w1, 4608,   32, 32, 32, 1, 2},
        {w2, 13824,  64, 32, 32, 2, 2},
        {w3, 32256,  64, 64, 32, 2, 4},
        {w4, 69120,  64, 64, 32, 2, 4},
        {w5, 105984, 32, 64, 32, 1, 4},
        {w6, 124416, 32, 32, 32, 1, 2},
        {w7, 133632,  2, 32, 16, 1, 2},
    };
    for (int i = 0; i < 8; i++) {
        int total = wl[i].GRPS * wl[i].CBLKS * 9 * wl[i].COUTP * 16;
        wconv_kernel<<<(total + 255) / 256, 256>>>(
            wl[i].w, WH + wl[i].off, WL + wl[i].off,
            wl[i].COUT, wl[i].CIN, wl[i].COUTP, wl[i].GRPS, wl[i].CBLKS);
    }

    // ---- flow net ----
    // conv0: 3->32 @512 relu            (x -> A)
    conv_mma_kernel<2, 1><<<dim3(8, 64, 4 * 1), 256, SMEM_NCT2>>>(
        x, WH + 0, WL + 0, b0, A, 512, 512, 3, 32, 1, 1);
    // conv1: 32->32 @512 relu           (A -> B)
    conv_mma_kernel<2, 1><<<dim3(8, 64, 4 * 1), 256, SMEM_NCT2>>>(
        A, WH + 4608, WL + 4608, b1, Bb, 512, 512, 32, 32, 2, 1);
    // pool: 512->256                    (B -> A)
    {
        int total = BATCH * 32 * 256 * 256;
        pool2_kernel<<<(total + 255) / 256, 256>>>(Bb, A, total, 256, 256);
    }
    // conv2: 32->64 @256 relu           (A -> B)
    conv_mma_kernel<2, 1><<<dim3(4, 32, 4 * 2), 256, SMEM_NCT2>>>(
        A, WH + 13824, WL + 13824, b2, Bb, 256, 256, 32, 64, 2, 2);
    // conv3: 64->64 @256 relu           (B -> A)
    conv_mma_kernel<2, 1><<<dim3(4, 32, 4 * 2), 256, SMEM_NCT2>>>(
        Bb, WH + 32256, WL + 32256, b3, A, 256, 256, 64, 64, 4, 2);
    // pool: 256->128                    (A -> B)
    {
        int total = BATCH * 64 * 128 * 128;
        pool2_kernel<<<(total + 255) / 256, 256>>>(A, Bb, total, 128, 128);
    }
    // up: 128->256                      (B -> A)
    {
        int total = BATCH * 64 * 256 * 256;
        up2_kernel<<<(total + 255) / 256, 256>>>(Bb, A, total, 128, 128);
    }
    // conv4: 64->64 @256 relu           (A -> B)
    conv_mma_kernel<2, 1><<<dim3(4, 32, 4 * 2), 256, SMEM_NCT2>>>(
        A, WH + 69120, WL + 69120, b4, Bb, 256, 256, 64, 64, 4, 2);
    // conv5: 64->32 @256 relu           (B -> A)
    conv_mma_kernel<2, 1><<<dim3(4, 32, 4 * 1), 256, SMEM_NCT2>>>(
        Bb, WH + 105984, WL + 105984, b5, A, 256, 256, 64, 32, 4, 1);
    // up: 256->512                      (A -> B)
    {
        int total = BATCH * 32 * 512 * 512;
        up2_kernel<<<(total + 255) / 256, 256>>>(A, Bb, total, 256, 256);
    }
    // conv6: 32->32 @512 relu           (B -> A)
    conv_mma_kernel<2, 1><<<dim3(8, 64, 4 * 1), 256, SMEM_NCT2>>>(
        Bb, WH + 124416, WL + 124416, b6, A, 512, 512, 32, 32, 2, 1);
    // conv7: 32->2 @512 tanh            (A -> flow)
    conv_mma_kernel<1, 2><<<dim3(8, 64, 4 * 1), 256, SMEM_NCT1>>>(
        A, WH + 133632, WL + 133632, b7, flow, 512, 512, 32, 2, 2, 1);

    // deformed grid
    {
        int total = BATCH * IMG_H * IMG_W;
        deform_kernel<<<(total + 255) / 256, 256>>>(flow, temp, def);
    }
    // patches
    patches_kernel<<<dim3(BATCH * NPATCH), 256>>>(x, def, patches);
}

// round 8
// speedup vs baseline: 2.8689x; 1.4440x over previous
#include <cuda_runtime.h>
#include <cuda_bf16.h>
#include <math.h>

// ---------------------------------------------------------------------------
// Problem constants
// ---------------------------------------------------------------------------
#define BATCH 4
#define IMG_H 512
#define IMG_W 512
#define PATCH 64
#define STRIDE_ 32
#define NPATCH 256
#define PATCHES_ELEMS (BATCH * NPATCH * 3 * PATCH * PATCH)   // 12,582,912
#define FLOW_ELEMS    (BATCH * 2 * IMG_H * IMG_W)            //  2,097,152

// Scratch (device globals). Each 33.5M floats = 67.1M bf16 = hi+lo planes
// of one activation (max plane = 33,554,432 bf16 elements).
__device__ __align__(256) float g_bufA[33554432];
__device__ __align__(256) float g_bufB[33554432];
#define PLANE_ELEMS 33554432

// Preconverted weights (bf16 hi/lo, pos16-permuted).
#define WSCRATCH 138240
__device__ __align__(256) __nv_bfloat16 g_wh[WSCRATCH];
__device__ __align__(256) __nv_bfloat16 g_wl[WSCRATCH];

// ---------------------------------------------------------------------------
// helpers
// ---------------------------------------------------------------------------
__device__ __forceinline__ void cp_async16(void* smem_dst, const void* gptr) {
    unsigned sa = (unsigned)__cvta_generic_to_shared(smem_dst);
    asm volatile("cp.async.cg.shared.global [%0], [%1], 16;" :: "r"(sa), "l"(gptr));
}
__device__ __forceinline__ void cp_commit() { asm volatile("cp.async.commit_group;"); }
__device__ __forceinline__ void cp_wait0()  { asm volatile("cp.async.wait_group 0;"); }

__device__ __forceinline__ void mma16816(float* c, const unsigned* a, unsigned b0, unsigned b1) {
    asm volatile(
        "mma.sync.aligned.m16n8k16.row.col.f32.bf16.bf16.f32 "
        "{%0,%1,%2,%3}, {%4,%5,%6,%7}, {%8,%9}, {%0,%1,%2,%3};"
        : "+f"(c[0]), "+f"(c[1]), "+f"(c[2]), "+f"(c[3])
        : "r"(a[0]), "r"(a[1]), "r"(a[2]), "r"(a[3]), "r"(b0), "r"(b1));
}

// ci permutation: pairs (2i,2i+1); group i&3 at base 4*(i&3), half i>>2 at +2.
// pos16(2q)=4q, pos16(2q+1)=4q+1, pos16(2q+8)=4q+2, pos16(2q+9)=4q+3 (q=0..3)
__device__ __forceinline__ int pos16(int ci) {
    return (((ci >> 1) & 3) << 2) + (((ci >> 3) & 1) << 1) + (ci & 1);
}
__device__ __forceinline__ void bf16split(float v, __nv_bfloat16& h, __nv_bfloat16& l) {
    h = __float2bfloat16(v);
    l = __float2bfloat16(v - __bfloat162float(h));
}

// ---------------------------------------------------------------------------
// Weight preconversion: fp32 [COUT][CIN][3][3] ->
// bf16 hi/lo planes [grp][cinblk][tap][co(COUTP)][pos16(ci)], zero-padded.
// ---------------------------------------------------------------------------
__global__ void wconv_kernel(const float* __restrict__ w,
                             __nv_bfloat16* __restrict__ dh,
                             __nv_bfloat16* __restrict__ dl,
                             int COUT, int CIN, int COUTP, int GRPS, int CBLKS)
{
    int total = GRPS * CBLKS * 9 * COUTP * 16;
    int idx = blockIdx.x * blockDim.x + threadIdx.x;
    if (idx >= total) return;
    int ci = idx & 15;
    int t = idx >> 4;
    int co = t % COUTP;  t /= COUTP;
    int tap = t % 9;     t /= 9;
    int cb = t % CBLKS;
    int grp = t / CBLKS;
    int co_g = grp * COUTP + co;
    int ci_g = cb * 16 + ci;
    float v = 0.f;
    if (co_g < COUT && ci_g < CIN)
        v = w[((size_t)co_g * CIN + ci_g) * 9 + tap];
    __nv_bfloat16 h, l;
    bf16split(v, h, l);
    int base = idx & ~15;
    dh[base + pos16(ci)] = h;
    dl[base + pos16(ci)] = l;
}

// ---------------------------------------------------------------------------
// x (fp32 NCHW, C=3) -> act layout [b][cb=0][y][x][pos16(ci)], ci>=3 zero
// ---------------------------------------------------------------------------
__global__ void xcvt_kernel(const float* __restrict__ x,
                            __nv_bfloat16* __restrict__ ohi,
                            __nv_bfloat16* __restrict__ olo)
{
    int idx = blockIdx.x * blockDim.x + threadIdx.x;
    int total = BATCH * IMG_H * IMG_W * 16;
    if (idx >= total) return;
    int ci = idx & 15;
    int p = idx >> 4;
    int xx = p % IMG_W;
    int yy = (p / IMG_W) % IMG_H;
    int b  = p / (IMG_W * IMG_H);
    float v = 0.f;
    if (ci < 3)
        v = x[((size_t)(b * 3 + ci) * IMG_H + yy) * IMG_W + xx];
    __nv_bfloat16 h, l;
    bf16split(v, h, l);
    size_t o = ((size_t)p << 4) + pos16(ci);
    ohi[o] = h;
    olo[o] = l;
}

// ---------------------------------------------------------------------------
// Implicit-GEMM 3x3 conv via mma.sync bf16 (3-term hi/lo split).
// Input/weights already bf16 hi/lo in pos16 layout -> staging = raw cp.async.
// CTA: 256 threads (8 warps). Output tile: 64 wide x 8 tall x COUTP couts.
// OUTF32=0: write bf16 hi/lo act layout (ACT=relu).  OUTF32=1: fp32 NCHW+tanh.
// ---------------------------------------------------------------------------
template <int NCT, int ACT, int OUTF32>
__global__ void __launch_bounds__(256, 2)
conv_mma_kernel(const __nv_bfloat16* __restrict__ ghi,
                const __nv_bfloat16* __restrict__ glo,
                const __nv_bfloat16* __restrict__ gwh,
                const __nv_bfloat16* __restrict__ gwl,
                const float* __restrict__ bias,
                __nv_bfloat16* __restrict__ ohi,
                __nv_bfloat16* __restrict__ olo,
                float* __restrict__ of32,
                int H, int W, int CBIN, int COUT, int GRPS)
{
    constexpr int COUTP = NCT * 16;
    constexpr int IN_PLANE = 10 * 68 * 16;     // 10880 bf16
    constexpr int WPL = 9 * COUTP * 16;
    extern __shared__ char smraw[];
    __nv_bfloat16* s_hi = (__nv_bfloat16*)smraw;
    __nv_bfloat16* s_lo = s_hi + IN_PLANE;
    __nv_bfloat16* s_wh = s_hi + 2 * IN_PLANE;
    __nv_bfloat16* s_wl = s_wh + WPL;

    const int bx = blockIdx.x * 64;
    const int by = blockIdx.y * 8;
    const int grp = blockIdx.z % GRPS;
    const int b   = blockIdx.z / GRPS;

    const int tid  = threadIdx.x;
    const int warp = tid >> 5;
    const int lane = tid & 31;
    const int gid  = lane >> 2;   // 0..7
    const int qid  = lane & 3;    // 0..3

    float acc[NCT][8][4];
#pragma unroll
    for (int ct = 0; ct < NCT; ct++)
#pragma unroll
        for (int nt = 0; nt < 8; nt++) {
            acc[ct][nt][0] = 0.f; acc[ct][nt][1] = 0.f;
            acc[ct][nt][2] = 0.f; acc[ct][nt][3] = 0.f;
        }

    for (int cb = 0; cb < CBIN; cb++) {
        __syncthreads();
        // ---- stage weights (raw bf16 copy) ----
        {
            const __nv_bfloat16* pwh = gwh + ((size_t)grp * CBIN + cb) * WPL;
            const __nv_bfloat16* pwl = gwl + ((size_t)grp * CBIN + cb) * WPL;
            for (int idx = tid * 8; idx < WPL; idx += 2048) {
                cp_async16(s_wh + idx, pwh + idx);
                cp_async16(s_wl + idx, pwl + idx);
            }
        }
        // ---- stage input chunk: 10x66 pixels, 32B/pixel/plane raw copy ----
        for (int p = tid; p < 660; p += 256) {
            int row = p / 66;
            int col = p - row * 66;
            int gy = by + row - 1;
            int gx = bx + col - 1;
            int soff = (row * 68 + col) * 16;
            if (gy >= 0 && gy < H && gx >= 0 && gx < W) {
                size_t g = ((((size_t)b * CBIN + cb) * H + gy) * W + gx) << 4;
                cp_async16(s_hi + soff,     ghi + g);
                cp_async16(s_hi + soff + 8, ghi + g + 8);
                cp_async16(s_lo + soff,     glo + g);
                cp_async16(s_lo + soff + 8, glo + g + 8);
            } else {
                uint4 z = make_uint4(0u, 0u, 0u, 0u);
                *(uint4*)(s_hi + soff) = z; *(uint4*)(s_hi + soff + 8) = z;
                *(uint4*)(s_lo + soff) = z; *(uint4*)(s_lo + soff + 8) = z;
            }
        }
        cp_commit();
        cp_wait0();
        __syncthreads();

        // ---- compute: 9 taps ----
        int ky = 0, kx = 0;
#pragma unroll 1
        for (int tap = 0; tap < 9; tap++) {
            unsigned ah[NCT][4], al[NCT][4];
            const int wbase = tap * COUTP * 16 + 4 * qid;
#pragma unroll
            for (int ct = 0; ct < NCT; ct++) {
                int co_l = ct * 16 + gid;
                uint2 h0 = *(const uint2*)(s_wh + wbase + co_l * 16);
                uint2 h1 = *(const uint2*)(s_wh + wbase + (co_l + 8) * 16);
                ah[ct][0] = h0.x; ah[ct][2] = h0.y;
                ah[ct][1] = h1.x; ah[ct][3] = h1.y;
                uint2 l0 = *(const uint2*)(s_wl + wbase + co_l * 16);
                uint2 l1 = *(const uint2*)(s_wl + wbase + (co_l + 8) * 16);
                al[ct][0] = l0.x; al[ct][2] = l0.y;
                al[ct][1] = l1.x; al[ct][3] = l1.y;
            }
            const int rowb = warp + ky;
#pragma unroll
            for (int nt = 0; nt < 8; nt++) {
                int colb = nt * 8 + gid + kx;
                int base = (rowb * 68 + colb) * 16 + 4 * qid;
                uint2 bh = *(const uint2*)(s_hi + base);
                uint2 bl = *(const uint2*)(s_lo + base);
#pragma unroll
                for (int ct = 0; ct < NCT; ct++) {
                    mma16816(acc[ct][nt], ah[ct], bh.x, bh.y);
                    mma16816(acc[ct][nt], ah[ct], bl.x, bl.y);
                    mma16816(acc[ct][nt], al[ct], bh.x, bh.y);
                }
            }
            if (++kx == 3) { kx = 0; ++ky; }
        }
    }

    // ---- epilogue ----
    const int gy = by + warp;
    if (OUTF32) {
        // fp32 NCHW output (+tanh), guarded against COUT
#pragma unroll
        for (int ct = 0; ct < NCT; ct++) {
            int co0r = grp * COUTP + ct * 16 + gid;
            int co1r = co0r + 8;
            bool ok0 = co0r < COUT;
            bool ok1 = co1r < COUT;
            float bv0 = ok0 ? bias[co0r] : 0.f;
            float bv1 = ok1 ? bias[co1r] : 0.f;
#pragma unroll
            for (int nt = 0; nt < 8; nt++) {
                int gxv = bx + nt * 8 + 2 * qid;
                if (ok0) {
                    float v0 = tanhf(acc[ct][nt][0] + bv0);
                    float v1 = tanhf(acc[ct][nt][1] + bv0);
                    *(float2*)&of32[((size_t)(b * COUT + co0r) * H + gy) * W + gxv]
                        = make_float2(v0, v1);
                }
                if (ok1) {
                    float v0 = tanhf(acc[ct][nt][2] + bv1);
                    float v1 = tanhf(acc[ct][nt][3] + bv1);
                    *(float2*)&of32[((size_t)(b * COUT + co1r) * H + gy) * W + gxv]
                        = make_float2(v0, v1);
                }
            }
        }
    } else {
        const int nCBo = COUT >> 4;
        const int slot0 = pos16(gid);       // co_g & 15 == gid
        const int slot1 = slot0 + 2;        // pos16(gid + 8)
#pragma unroll
        for (int ct = 0; ct < NCT; ct++) {
            int co_g = grp * COUTP + ct * 16 + gid;
            int cbo = co_g >> 4;
            float bv0 = bias[co_g];
            float bv1 = bias[co_g + 8];
#pragma unroll
            for (int nt = 0; nt < 8; nt++) {
                int gxv = bx + nt * 8 + 2 * qid;
                size_t g = ((((size_t)b * nCBo + cbo) * H + gy) * W + gxv) << 4;
                float v0 = acc[ct][nt][0] + bv0;
                float v1 = acc[ct][nt][1] + bv0;
                float v2 = acc[ct][nt][2] + bv1;
                float v3 = acc[ct][nt][3] + bv1;
                if (ACT == 1) {
                    v0 = fmaxf(v0, 0.f); v1 = fmaxf(v1, 0.f);
                    v2 = fmaxf(v2, 0.f); v3 = fmaxf(v3, 0.f);
                }
                __nv_bfloat16 h, l;
                bf16split(v0, h, l); ohi[g + slot0]      = h; olo[g + slot0]      = l;
                bf16split(v1, h, l); ohi[g + 16 + slot0] = h; olo[g + 16 + slot0] = l;
                bf16split(v2, h, l); ohi[g + slot1]      = h; olo[g + slot1]      = l;
                bf16split(v3, h, l); ohi[g + 16 + slot1] = h; olo[g + 16 + slot1] = l;
            }
        }
    }
}

// ---------------------------------------------------------------------------
// MaxPool 2x2 stride 2 on bf16 hi/lo act layout (slot-preserving)
// ---------------------------------------------------------------------------
__global__ void pool_bf16(const __nv_bfloat16* __restrict__ ihi,
                          const __nv_bfloat16* __restrict__ ilo,
                          __nv_bfloat16* __restrict__ ohi,
                          __nv_bfloat16* __restrict__ olo,
                          int total, int Hout, int Wout)
{
    int idx = blockIdx.x * blockDim.x + threadIdx.x;
    if (idx >= total) return;
    int slot = idx & 15;
    int p = idx >> 4;
    int x = p % Wout;
    int t = p / Wout;
    int y = t % Hout;
    int c = t / Hout;
    int Win = 2 * Wout;
    size_t base = (((size_t)c * 2 * Hout + 2 * y) * Win + 2 * x) * 16 + slot;
    size_t o00 = base, o01 = base + 16;
    size_t o10 = base + (size_t)Win * 16, o11 = o10 + 16;
    float v00 = __bfloat162float(ihi[o00]) + __bfloat162float(ilo[o00]);
    float v01 = __bfloat162float(ihi[o01]) + __bfloat162float(ilo[o01]);
    float v10 = __bfloat162float(ihi[o10]) + __bfloat162float(ilo[o10]);
    float v11 = __bfloat162float(ihi[o11]) + __bfloat162float(ilo[o11]);
    size_t best = o00; float bv = v00;
    if (v01 > bv) { bv = v01; best = o01; }
    if (v10 > bv) { bv = v10; best = o10; }
    if (v11 > bv) { bv = v11; best = o11; }
    ohi[idx] = ihi[best];
    olo[idx] = ilo[best];
}

// ---------------------------------------------------------------------------
// Bilinear upsample x2 on bf16 hi/lo act layout (slot-preserving)
// ---------------------------------------------------------------------------
__global__ void up_bf16(const __nv_bfloat16* __restrict__ ihi,
                        const __nv_bfloat16* __restrict__ ilo,
                        __nv_bfloat16* __restrict__ ohi,
                        __nv_bfloat16* __restrict__ olo,
                        int total, int Hin, int Win)
{
    int idx = blockIdx.x * blockDim.x + threadIdx.x;
    if (idx >= total) return;
    int slot = idx & 15;
    int p = idx >> 4;
    int Hout = 2 * Hin, Wout = 2 * Win;
    int ox = p % Wout;
    int t = p / Wout;
    int oy = t % Hout;
    int c = t / Hout;

    float fy = (oy + 0.5f) * 0.5f - 0.5f;
    float fx = (ox + 0.5f) * 0.5f - 0.5f;
    int y0 = (int)floorf(fy);
    int x0 = (int)floorf(fx);
    float wy = fy - (float)y0;
    float wx = fx - (float)x0;
    int y0c = max(y0, 0), y1c = min(y0 + 1, Hin - 1);
    int x0c = max(x0, 0), x1c = min(x0 + 1, Win - 1);

    size_t cb = (size_t)c * Hin;
    size_t o00 = ((cb + y0c) * Win + x0c) * 16 + slot;
    size_t o01 = ((cb + y0c) * Win + x1c) * 16 + slot;
    size_t o10 = ((cb + y1c) * Win + x0c) * 16 + slot;
    size_t o11 = ((cb + y1c) * Win + x1c) * 16 + slot;
    float v00 = __bfloat162float(ihi[o00]) + __bfloat162float(ilo[o00]);
    float v01 = __bfloat162float(ihi[o01]) + __bfloat162float(ilo[o01]);
    float v10 = __bfloat162float(ihi[o10]) + __bfloat162float(ilo[o10]);
    float v11 = __bfloat162float(ihi[o11]) + __bfloat162float(ilo[o11]);
    float v = (1.f - wy) * ((1.f - wx) * v00 + wx * v01)
            +        wy  * ((1.f - wx) * v10 + wx * v11);
    __nv_bfloat16 h, l;
    bf16split(v, h, l);
    ohi[idx] = h;
    olo[idx] = l;
}

// ---------------------------------------------------------------------------
// deformed = base_grid + flow^T * temp
// ---------------------------------------------------------------------------
__global__ void deform_kernel(const float* __restrict__ flow,
                              const float* __restrict__ temp,
                              float* __restrict__ def)
{
    int idx = blockIdx.x * blockDim.x + threadIdx.x;
    int total = BATCH * IMG_H * IMG_W;
    if (idx >= total) return;
    int w = idx % IMG_W;
    int h = (idx / IMG_W) % IMG_H;
    int b = idx / (IMG_W * IMG_H);
    float gx = -1.0f + 2.0f * (float)w / (float)(IMG_W - 1);
    float gy = -1.0f + 2.0f * (float)h / (float)(IMG_H - 1);
    float t = temp[0];
    float fx = flow[((size_t)(b * 2 + 0) * IMG_H + h) * IMG_W + w];
    float fy = flow[((size_t)(b * 2 + 1) * IMG_H + h) * IMG_W + w];
    def[(size_t)idx * 2 + 0] = gx + fx * t;
    def[(size_t)idx * 2 + 1] = gy + fy * t;
}

// ---------------------------------------------------------------------------
// Patch extraction (grid_sample bilinear, zeros padding)
// ---------------------------------------------------------------------------
__global__ void patches_kernel(const float* __restrict__ x,
                               const float* __restrict__ def,
                               float* __restrict__ out)
{
    int bn = blockIdx.x;
    int b = bn >> 8;
    int n = bn & 255;
    int hy = n >> 4;
    int wx = n & 15;
    const float* dptr = def + (((size_t)(b * IMG_H + hy * STRIDE_) * IMG_W) + wx * STRIDE_) * 2;
    float cx = dptr[0];
    float cy = dptr[1];

    for (int p = threadIdx.x; p < PATCH * PATCH; p += blockDim.x) {
        int i = p >> 6;
        int j = p & 63;
        float pxv = -1.0f + 2.0f * (float)j / (float)(PATCH - 1);
        float pyv = -1.0f + 2.0f * (float)i / (float)(PATCH - 1);
        float gx = cx + pxv * ((float)PATCH / (float)IMG_W);
        float gy = cy + pyv * ((float)PATCH / (float)IMG_H);
        float ix = ((gx + 1.0f) * (float)IMG_W - 1.0f) * 0.5f;
        float iy = ((gy + 1.0f) * (float)IMG_H - 1.0f) * 0.5f;
        float x0f = floorf(ix), y0f = floorf(iy);
        float wx1 = ix - x0f, wy1 = iy - y0f;
        int x0 = (int)x0f, y0 = (int)y0f;
        int x1 = x0 + 1, y1 = y0 + 1;
        bool vx0 = (x0 >= 0) & (x0 <= IMG_W - 1);
        bool vx1 = (x1 >= 0) & (x1 <= IMG_W - 1);
        bool vy0 = (y0 >= 0) & (y0 <= IMG_H - 1);
        bool vy1 = (y1 >= 0) & (y1 <= IMG_H - 1);
        int x0c = min(max(x0, 0), IMG_W - 1);
        int x1c = min(max(x1, 0), IMG_W - 1);
        int y0c = min(max(y0, 0), IMG_H - 1);
        int y1c = min(max(y1, 0), IMG_H - 1);
        float w00 = (1.f - wx1) * (1.f - wy1) * (float)(vx0 && vy0);
        float w10 = wx1 * (1.f - wy1) * (float)(vx1 && vy0);
        float w01 = (1.f - wx1) * wy1 * (float)(vx0 && vy1);
        float w11 = wx1 * wy1 * (float)(vx1 && vy1);

#pragma unroll
        for (int c = 0; c < 3; c++) {
            const float* img = x + (size_t)(b * 3 + c) * IMG_H * IMG_W;
            float v = img[y0c * IMG_W + x0c] * w00
                    + img[y0c * IMG_W + x1c] * w10
                    + img[y1c * IMG_W + x0c] * w01
                    + img[y1c * IMG_W + x1c] * w11;
            out[((size_t)(bn)*3 + c) * (PATCH * PATCH) + p] = v;
        }
    }
}

// ---------------------------------------------------------------------------
// Launch
// ---------------------------------------------------------------------------
#define SMEM_NCT2 ((2 * 10880 + 2 * 4608) * 2)   // 61952 B
#define SMEM_NCT1 ((2 * 10880 + 2 * 2304) * 2)   // 52736 B

extern "C" void kernel_launch(void* const* d_in, const int* in_sizes, int n_in,
                              void* d_out, int out_size)
{
    const float* x  = (const float*)d_in[0];
    const float* w0 = (const float*)d_in[1];  const float* b0 = (const float*)d_in[2];
    const float* w1 = (const float*)d_in[3];  const float* b1 = (const float*)d_in[4];
    const float* w2 = (const float*)d_in[5];  const float* b2 = (const float*)d_in[6];
    const float* w3 = (const float*)d_in[7];  const float* b3 = (const float*)d_in[8];
    const float* w4 = (const float*)d_in[9];  const float* b4 = (const float*)d_in[10];
    const float* w5 = (const float*)d_in[11]; const float* b5 = (const float*)d_in[12];
    const float* w6 = (const float*)d_in[13]; const float* b6 = (const float*)d_in[14];
    const float* w7 = (const float*)d_in[15]; const float* b7 = (const float*)d_in[16];
    const float* temp = (const float*)d_in[17];

    float* out     = (float*)d_out;
    float* patches = out;
    float* flow    = out + PATCHES_ELEMS;
    float* def     = out + PATCHES_ELEMS + FLOW_ELEMS;

    float* A;  cudaGetSymbolAddress((void**)&A, g_bufA);
    float* Bb; cudaGetSymbolAddress((void**)&Bb, g_bufB);
    __nv_bfloat16* WH; cudaGetSymbolAddress((void**)&WH, g_wh);
    __nv_bfloat16* WL; cudaGetSymbolAddress((void**)&WL, g_wl);

    __nv_bfloat16* Ahi = (__nv_bfloat16*)A;
    __nv_bfloat16* Alo = Ahi + PLANE_ELEMS;
    __nv_bfloat16* Bhi = (__nv_bfloat16*)Bb;
    __nv_bfloat16* Blo = Bhi + PLANE_ELEMS;

    cudaFuncSetAttribute((const void*)conv_mma_kernel<2, 1, 0>,
                         cudaFuncAttributeMaxDynamicSharedMemorySize, SMEM_NCT2);
    cudaFuncSetAttribute((const void*)conv_mma_kernel<1, 2, 1>,
                         cudaFuncAttributeMaxDynamicSharedMemorySize, SMEM_NCT1);

    // ---- preconvert weights ----
    struct { const float* w; int off, COUT, CIN, COUTP, GRPS, CBLKS; } wl[8] = {
        {w0, 0,      32,  3, 32, 1, 1},
        {w1, 4608,   32, 32, 32, 1, 2},
        {w2, 13824,  64, 32, 32, 2, 2},
        {w3, 32256,  64, 64, 32, 2, 4},
        {w4, 69120,  64, 64, 32, 2, 4},
        {w5, 105984, 32, 64, 32, 1, 4},
        {w6, 124416, 32, 32, 32, 1, 2},
        {w7, 133632,  2, 32, 16, 1, 2},
    };
    for (int i = 0; i < 8; i++) {
        int total = wl[i].GRPS * wl[i].CBLKS * 9 * wl[i].COUTP * 16;
        wconv_kernel<<<(total + 255) / 256, 256>>>(
            wl[i].w, WH + wl[i].off, WL + wl[i].off,
            wl[i].COUT, wl[i].CIN, wl[i].COUTP, wl[i].GRPS, wl[i].CBLKS);
    }

    // ---- x -> bf16 act layout (B) ----
    {
        int total = BATCH * IMG_H * IMG_W * 16;
        xcvt_kernel<<<(total + 255) / 256, 256>>>(x, Bhi, Blo);
    }

    // ---- flow net (ping-pong B <-> A) ----
    // conv0: 3->32 @512 relu  (B -> A)
    conv_mma_kernel<2, 1, 0><<<dim3(8, 64, 4), 256, SMEM_NCT2>>>(
        Bhi, Blo, WH + 0, WL + 0, b0, Ahi, Alo, nullptr, 512, 512, 1, 32, 1);
    // conv1: 32->32 @512 relu (A -> B)
    conv_mma_kernel<2, 1, 0><<<dim3(8, 64, 4), 256, SMEM_NCT2>>>(
        Ahi, Alo, WH + 4608, WL + 4608, b1, Bhi, Blo, nullptr, 512, 512, 2, 32, 1);
    // pool: 512->256          (B -> A)
    {
        int total = BATCH * 2 * 256 * 256 * 16;
        pool_bf16<<<(total + 255) / 256, 256>>>(Bhi, Blo, Ahi, Alo, total, 256, 256);
    }
    // conv2: 32->64 @256 relu (A -> B)
    conv_mma_kernel<2, 1, 0><<<dim3(4, 32, 4 * 2), 256, SMEM_NCT2>>>(
        Ahi, Alo, WH + 13824, WL + 13824, b2, Bhi, Blo, nullptr, 256, 256, 2, 64, 2);
    // conv3: 64->64 @256 relu (B -> A)
    conv_mma_kernel<2, 1, 0><<<dim3(4, 32, 4 * 2), 256, SMEM_NCT2>>>(
        Bhi, Blo, WH + 32256, WL + 32256, b3, Ahi, Alo, nullptr, 256, 256, 4, 64, 2);
    // pool: 256->128          (A -> B)
    {
        int total = BATCH * 4 * 128 * 128 * 16;
        pool_bf16<<<(total + 255) / 256, 256>>>(Ahi, Alo, Bhi, Blo, total, 128, 128);
    }
    // up: 128->256            (B -> A)
    {
        int total = BATCH * 4 * 256 * 256 * 16;
        up_bf16<<<(total + 255) / 256, 256>>>(Bhi, Blo, Ahi, Alo, total, 128, 128);
    }
    // conv4: 64->64 @256 relu (A -> B)
    conv_mma_kernel<2, 1, 0><<<dim3(4, 32, 4 * 2), 256, SMEM_NCT2>>>(
        Ahi, Alo, WH + 69120, WL + 69120, b4, Bhi, Blo, nullptr, 256, 256, 4, 64, 2);
    // conv5: 64->32 @256 relu (B -> A)
    conv_mma_kernel<2, 1, 0><<<dim3(4, 32, 4), 256, SMEM_NCT2>>>(
        Bhi, Blo, WH + 105984, WL + 105984, b5, Ahi, Alo, nullptr, 256, 256, 4, 32, 1);
    // up: 256->512            (A -> B)
    {
        int total = BATCH * 2 * 512 * 512 * 16;
        up_bf16<<<(total + 255) / 256, 256>>>(Ahi, Alo, Bhi, Blo, total, 256, 256);
    }
    // conv6: 32->32 @512 relu (B -> A)
    conv_mma_kernel<2, 1, 0><<<dim3(8, 64, 4), 256, SMEM_NCT2>>>(
        Bhi, Blo, WH + 124416, WL + 124416, b6, Ahi, Alo, nullptr, 512, 512, 2, 32, 1);
    // conv7: 32->2 @512 tanh  (A -> flow, fp32)
    conv_mma_kernel<1, 2, 1><<<dim3(8, 64, 4), 256, SMEM_NCT1>>>(
        Ahi, Alo, WH + 133632, WL + 133632, b7, nullptr, nullptr, flow, 512, 512, 2, 2, 1);

    // deformed grid
    {
        int total = BATCH * IMG_H * IMG_W;
        deform_kernel<<<(total + 255) / 256, 256>>>(flow, temp, def);
    }
    // patches
    patches_kernel<<<dim3(BATCH * NPATCH), 256>>>(x, def, patches);
}